// round 7
// baseline (speedup 1.0000x reference)
#include <cuda_runtime.h>
#include <cstdint>

// Pink noise: 6-pole diagonal IIR + 1-sample delay, exact segment-resident scan.
// white[B, L] -> pink[B, L], L=65536, one block per channel.
//
// v5: separate output buffer (no in-place overwrite) + half-phased pipeline:
// as soon as a column-half of the white tile W is fully consumed by pass B,
// the NEXT segment's matching half is cp.async'd into the freed slots, so
// staging latency hides under ~2000 cycles of compute. W uses an XOR slot
// swizzle (stride 32, conflict-free for coalesced staging AND per-thread
// sequential consume). All-warp redundant combine removes one barrier.

#define NT      512
#define SEG     16384
#define NSEG    4
#define LROW    65536
#define NW      16
#define WSTRIDE 32
#define OSTRIDE 20
#define W_FLOATS (NT * WSTRIDE)           // 16384 floats = 64KB
#define O_FLOATS (NT * OSTRIDE)           // 10240 floats = 40KB
#define SMEM_FLOATS (W_FLOATS + O_FLOATS) // 106496 bytes total

typedef unsigned long long ull;

__device__ __forceinline__ ull pk2(float lo, float hi) {
    ull r; asm("mov.b64 %0, {%1, %2};" : "=l"(r) : "f"(lo), "f"(hi)); return r;
}
__device__ __forceinline__ void upk2(ull v, float& lo, float& hi) {
    asm("mov.b64 {%0, %1}, %2;" : "=f"(lo), "=f"(hi) : "l"(v));
}
__device__ __forceinline__ ull ffma2(ull a, ull b, ull c) {
    ull d; asm("fma.rn.f32x2 %0, %1, %2, %3;" : "=l"(d) : "l"(a), "l"(b), "l"(c)); return d;
}
__device__ __forceinline__ ull fmul2(ull a, ull b) {
    ull d; asm("mul.rn.f32x2 %0, %1, %2;" : "=l"(d) : "l"(a), "l"(b)); return d;
}

__device__ __forceinline__ void cpasync16(uint32_t dst, const void* src) {
    asm volatile("cp.async.cg.shared.global [%0], [%1], 16;" :: "r"(dst), "l"(src));
}
#define CP_COMMIT() asm volatile("cp.async.commit_group;" ::: "memory")
#define CP_WAIT0()  asm volatile("cp.async.wait_group 0;" ::: "memory")
#define CP_WAIT1()  asm volatile("cp.async.wait_group 1;" ::: "memory")

// Swizzled word slot (within a 32-word row) for float4 group q of row t.
// Conflict-free: staging (8 consecutive f = one row, q spans 0..7 -> 8 distinct
// slots) and consume (8 consecutive t at fixed q -> all 8 (t>>2&1, t&3) combos).
__device__ __forceinline__ int wslot(int q, int t) {
    return ((((q >> 2) ^ (t >> 2)) & 1) << 4) | (((q ^ t) & 3) << 2);
}

// Stage half h (float4 groups 4h..4h+3 of every row) of a segment into W.
__device__ __forceinline__ void stage_half(float* W, const float* __restrict__ gseg,
                                           int h, int tid) {
    uint32_t base = (uint32_t)__cvta_generic_to_shared(W);
#pragma unroll
    for (int r = 0; r < 4; r++) {
        int g = tid + r * NT;         // [0, 2048)
        int j = g >> 2;               // row
        int i = (g & 3) + 4 * h;      // float4 group within row
        cpasync16(base + (uint32_t)(j * WSTRIDE + wslot(i, j)) * 4u,
                  gseg + ((size_t)j * 8 + i) * 4);
    }
}

__global__ void __launch_bounds__(NT, 2)
pink_kernel(const float* __restrict__ white, float* __restrict__ out) {
    extern __shared__ float smem[];
    float* Wt = smem;                     // white tile, swizzled
    float* Ob = smem + W_FLOATS;          // output staging buffer (half segment)
    __shared__ float warpT[NW][6];

    const float A0 = 0.99886f, A1 = 0.99332f, A2 = 0.969f,
                A3 = 0.8665f,  A4 = 0.55f,    A5 = -0.7616f;
    const float OC0 = 0.11f * 0.0555179f, OC1 = 0.11f * 0.0750759f,
                OC2 = 0.11f * 0.153852f,  OC3 = 0.11f * 0.3104856f,
                OC4 = 0.11f * 0.5329522f, OC5 = 0.11f * -0.016898f;
    const float OB6 = 0.11f * 0.115926f, ODIR = 0.11f * 0.5362f;

    const int tid  = threadIdx.x;
    const int lane = tid & 31;
    const int wid  = tid >> 5;
    const float* wrow = white + (size_t)blockIdx.x * LROW;
    float*       orow = out   + (size_t)blockIdx.x * LROW;

    // Kick off both halves of segment 0 immediately (2 commit groups).
    stage_half(Wt, wrow, 0, tid); CP_COMMIT();
    stage_half(Wt, wrow, 1, tid); CP_COMMIT();

    const ull A01 = pk2(A0, A1), A23 = pk2(A2, A3), A45 = pk2(A4, A5);
    const ull C01 = pk2(OC0, OC1), C23 = pk2(OC2, OC3), C45 = pk2(OC4, OC5);
    const ull ODB = pk2(ODIR, OB6);

    // Power tables: m = a^32, mlane = m^lane, m32w = (m^32)^wid, d512 = m^512.
    float m[6], mlane[6], m32w[6], d512[6];
    {
        const float a[6] = {A0, A1, A2, A3, A4, A5};
#pragma unroll
        for (int i = 0; i < 6; i++) {
            float t = a[i];
#pragma unroll
            for (int s = 0; s < 5; s++) t *= t;
            m[i] = t;                                  // a^32
            float b = t, r = 1.f; int e = lane;
#pragma unroll
            for (int s = 0; s < 5; s++) { if (e & 1) r *= b; b *= b; e >>= 1; }
            mlane[i] = r;                              // b == m^32 now
            float b2 = b, r2 = 1.f; int e2 = wid;
#pragma unroll
            for (int s = 0; s < 4; s++) { if (e2 & 1) r2 *= b2; b2 *= b2; e2 >>= 1; }
            m32w[i] = r2;
            float d = m[i];
#pragma unroll
            for (int sq = 0; sq < 9; sq++) d *= d;     // m^512 = a^16384
            d512[i] = d;
        }
    }

    float segState[6] = {0.f, 0.f, 0.f, 0.f, 0.f, 0.f};
    float w_carry = 0.f;

    const float* wr = Wt + tid * WSTRIDE;
    float*       obr = Ob + tid * OSTRIDE;

#pragma unroll 1
    for (int s = 0; s < NSEG; s++) {
        const float* gseg_next = wrow + (size_t)(s + 1) * SEG;

        // ---------------- Pass A (half-phased waits) ----------------
        CP_WAIT1();                       // half0 of this segment done
        __syncthreads();
        ull U01 = 0ull, U23 = 0ull, U45 = 0ull;
#pragma unroll
        for (int q = 0; q < 4; q++) {
            float4 wv = *reinterpret_cast<const float4*>(wr + wslot(q, tid));
            float ws[4] = {wv.x, wv.y, wv.z, wv.w};
#pragma unroll
            for (int c = 0; c < 4; c++) {
                ull W = pk2(ws[c], ws[c]);
                U01 = ffma2(A01, U01, W);
                U23 = ffma2(A23, U23, W);
                U45 = ffma2(A45, U45, W);
            }
        }
        CP_WAIT0();                       // half1 done
        __syncthreads();
#pragma unroll
        for (int q = 4; q < 8; q++) {
            float4 wv = *reinterpret_cast<const float4*>(wr + wslot(q, tid));
            float ws[4] = {wv.x, wv.y, wv.z, wv.w};
#pragma unroll
            for (int c = 0; c < 4; c++) {
                ull W = pk2(ws[c], ws[c]);
                U01 = ffma2(A01, U01, W);
                U23 = ffma2(A23, U23, W);
                U45 = ffma2(A45, U45, W);
            }
        }

        // ---------------- Block scan over chunk states ----------------
        float p[6];
        upk2(U01, p[0], p[1]); upk2(U23, p[2], p[3]); upk2(U45, p[4], p[5]);
        float mult[6];
#pragma unroll
        for (int i = 0; i < 6; i++) mult[i] = m[i];
#pragma unroll
        for (int o = 1; o < 32; o <<= 1) {
#pragma unroll
            for (int i = 0; i < 6; i++) {
                float up = __shfl_up_sync(0xffffffffu, p[i], o);
                if (lane >= o) p[i] = fmaf(mult[i], up, p[i]);
                mult[i] *= mult[i];
            }
        }
        // mult == m^32
        float excl[6];
#pragma unroll
        for (int i = 0; i < 6; i++) {
            float e = __shfl_up_sync(0xffffffffu, p[i], 1);
            excl[i] = (lane == 0) ? 0.f : e;
        }
        if (lane == 31) {
#pragma unroll
            for (int i = 0; i < 6; i++) warpT[wid][i] = p[i];
        }
        __syncthreads();

        // Redundant all-warp combine over the 16 warp totals (no 2nd barrier).
        float E[6], tot[6];
        {
            float t6[6], cm[6];
#pragma unroll
            for (int i = 0; i < 6; i++) {
                t6[i] = (lane < NW) ? warpT[lane][i] : 0.f;
                cm[i] = mult[i];                      // m^32
            }
#pragma unroll
            for (int o = 1; o < NW; o <<= 1) {
#pragma unroll
                for (int i = 0; i < 6; i++) {
                    float up = __shfl_up_sync(0xffffffffu, t6[i], o);
                    if (lane >= o) t6[i] = fmaf(cm[i], up, t6[i]);
                    cm[i] *= cm[i];
                }
            }
#pragma unroll
            for (int i = 0; i < 6; i++) {
                float pw = __shfl_sync(0xffffffffu, t6[i], (wid > 0) ? (wid - 1) : 0);
                if (wid == 0) pw = 0.f;
                tot[i] = __shfl_sync(0xffffffffu, t6[i], NW - 1);
                E[i] = fmaf(mlane[i], fmaf(m32w[i], segState[i], pw), excl[i]);
            }
        }

        // b6 carry reads (before any next-segment staging touches W).
        float prev_w;
        if (tid == 0) prev_w = w_carry;
        else {
            int pt = tid - 1;
            prev_w = Wt[pt * WSTRIDE + wslot(7, pt) + 3];
        }
        float w_carry_next = Wt[(NT - 1) * WSTRIDE + 3];   // wslot(7,511)==0
#pragma unroll
        for (int i = 0; i < 6; i++)
            segState[i] = fmaf(d512[i], segState[i], tot[i]);

        // ---------------- Pass B half 0 -> O ----------------
        U01 = pk2(E[0], E[1]); U23 = pk2(E[2], E[3]); U45 = pk2(E[4], E[5]);
#pragma unroll
        for (int q = 0; q < 4; q++) {
            float4 wv = *reinterpret_cast<const float4*>(wr + wslot(q, tid));
            float ws[4] = {wv.x, wv.y, wv.z, wv.w};
            float o4[4];
#pragma unroll
            for (int c = 0; c < 4; c++) {
                float w = ws[c];
                ull W = pk2(w, w);
                U01 = ffma2(A01, U01, W);
                U23 = ffma2(A23, U23, W);
                U45 = ffma2(A45, U45, W);
                ull P = ffma2(C01, U01, ffma2(C23, U23, fmul2(C45, U45)));
                ull T2 = ffma2(ODB, pk2(w, prev_w), P);
                float tlo, thi; upk2(T2, tlo, thi);
                o4[c] = tlo + thi;
                prev_w = w;
            }
            *reinterpret_cast<float4*>(obr + q * 4) = make_float4(o4[0], o4[1], o4[2], o4[3]);
        }
        __syncthreads();                  // O half0 ready; W half0 fully consumed
        if (s + 1 < NSEG) { stage_half(Wt, gseg_next, 0, tid); CP_COMMIT(); }
        // writeout half0
#pragma unroll
        for (int r = 0; r < 4; r++) {
            int g = tid + r * NT;
            int j = g >> 2, c = g & 3;
            float4 v = *reinterpret_cast<const float4*>(Ob + j * OSTRIDE + c * 4);
            *reinterpret_cast<float4*>(orow + (size_t)s * SEG + j * 32 + c * 4) = v;
        }
        __syncthreads();                  // writeout done reading O

        // ---------------- Pass B half 1 -> O ----------------
#pragma unroll
        for (int q = 4; q < 8; q++) {
            float4 wv = *reinterpret_cast<const float4*>(wr + wslot(q, tid));
            float ws[4] = {wv.x, wv.y, wv.z, wv.w};
            float o4[4];
#pragma unroll
            for (int c = 0; c < 4; c++) {
                float w = ws[c];
                ull W = pk2(w, w);
                U01 = ffma2(A01, U01, W);
                U23 = ffma2(A23, U23, W);
                U45 = ffma2(A45, U45, W);
                ull P = ffma2(C01, U01, ffma2(C23, U23, fmul2(C45, U45)));
                ull T2 = ffma2(ODB, pk2(w, prev_w), P);
                float tlo, thi; upk2(T2, tlo, thi);
                o4[c] = tlo + thi;
                prev_w = w;
            }
            *reinterpret_cast<float4*>(obr + (q - 4) * 4) = make_float4(o4[0], o4[1], o4[2], o4[3]);
        }
        __syncthreads();                  // O half1 ready; W half1 fully consumed
        if (s + 1 < NSEG) { stage_half(Wt, gseg_next, 1, tid); CP_COMMIT(); }
        // writeout half1
#pragma unroll
        for (int r = 0; r < 4; r++) {
            int g = tid + r * NT;
            int j = g >> 2, c = g & 3;
            float4 v = *reinterpret_cast<const float4*>(Ob + j * OSTRIDE + c * 4);
            *reinterpret_cast<float4*>(orow + (size_t)s * SEG + j * 32 + 16 + c * 4) = v;
        }

        w_carry = w_carry_next;
    }
}

extern "C" void kernel_launch(void* const* d_in, const int* in_sizes, int n_in,
                              void* d_out, int out_size) {
    const float* white = (const float*)d_in[0];
    float* out = (float*)d_out;
    int B = out_size / LROW;

    size_t smem = (size_t)SMEM_FLOATS * sizeof(float);   // 106496 bytes
    cudaFuncSetAttribute(pink_kernel, cudaFuncAttributeMaxDynamicSharedMemorySize,
                         (int)smem);
    pink_kernel<<<B, NT, smem>>>(white, out);
}